// round 11
// baseline (speedup 1.0000x reference)
#include <cuda_runtime.h>
#include <cuda_fp16.h>
#include <cstdint>

// HistoGAN histogram loss via mma.sync f16 + ldmatrix, K-contiguous swizzled
// operands, KC=64, double-buffered stages, one sync per chunk.
// 256-thread CTA: 6 producer warps (unchanged math), warps 6-7 do pixel prep,
// ALL 8 warps consume 12 m16n8 tiles each (48 acc regs) -> 16 warps/SM.
//
// Stacked output view (192 rows x 64 cols):
//   rows   0- 63 : G_AB = q1 x q2^T
//   rows  64-127 : G_AC = q1 x q3^T
//   rows 128-191 : G_BC = q2 x q3^T        (w = sqrt(Iy), q_i = w * k_i)
// Flips applied at the epilogue so g_G holds final-orientation histograms:
//   hist0[u,v]=G_AB[u,v]; hist1[u,v]=G_AC[63-u,v]; hist2[u,v]=G_BC[63-u,63-v]

#define EPSV  (6.4f / 255.0f)
#define NPIX  65536
#define PARTS 37
#define QSTEP 4.761904761904762f   /* 300/63 */
#define KC    64

#define P0_OFF  0
#define P1_OFF  8192
#define P2_OFF  16384
#define STAGEB  24576
#define DSMEMB  (2 * STAGEB)

typedef unsigned long long ull;

__device__ float g_G[8 * 3 * 4096];   // [B][3][64][64] pre-flipped hist
__device__ float g_sum[8];            // per-batch total mass
__device__ float g_acc;               // Hellinger sum accumulator
__device__ unsigned g_done;           // hell CTA completion counter

static __device__ __forceinline__ float rcpa(float x) {
    float r; asm("rcp.approx.f32 %0, %1;" : "=f"(r) : "f"(x)); return r;
}
static __device__ __forceinline__ uint32_t s2u(const void* p) {
    uint32_t a;
    asm("{ .reg .u64 t; cvta.to.shared.u64 t, %1; cvt.u32.u64 %0, t; }"
        : "=r"(a) : "l"(p));
    return a;
}
static __device__ __forceinline__ uint32_t packh2(float lo, float hi) {
    __half2 h = __floats2half2_rn(lo, hi);
    return *(uint32_t*)&h;
}
static __device__ __forceinline__ ull pk2(float v) {
    ull r; asm("mov.b64 %0, {%1, %1};" : "=l"(r) : "f"(v)); return r;
}
static __device__ __forceinline__ ull fma2(ull a, ull b, ull c) {
    ull d; asm("fma.rn.f32x2 %0, %1, %2, %3;" : "=l"(d)
               : "l"(a), "l"(b), "l"(c));
    return d;
}
static __device__ __forceinline__ float lo32(ull a) {
    return __uint_as_float((uint32_t)a);
}
static __device__ __forceinline__ float hi32(ull a) {
    return __uint_as_float((uint32_t)(a >> 32));
}
static __device__ __forceinline__ uint32_t hmul2(uint32_t a, uint32_t b) {
    uint32_t d; asm("mul.rn.f16x2 %0, %1, %2;" : "=r"(d) : "r"(a), "r"(b));
    return d;
}
static __device__ __forceinline__ void sts128(uint32_t addr, uint32_t w0,
        uint32_t w1, uint32_t w2, uint32_t w3) {
    asm volatile("st.shared.v4.b32 [%0], {%1,%2,%3,%4};"
        :: "r"(addr), "r"(w0), "r"(w1), "r"(w2), "r"(w3));
}
static __device__ __forceinline__ void ldmx4(uint32_t& r0, uint32_t& r1,
        uint32_t& r2, uint32_t& r3, uint32_t addr) {
    asm volatile("ldmatrix.sync.aligned.m8n8.x4.shared.b16 {%0,%1,%2,%3}, [%4];"
        : "=r"(r0), "=r"(r1), "=r"(r2), "=r"(r3) : "r"(addr));
}
static __device__ __forceinline__ void mma16(float* c,
        const uint32_t* a, uint32_t b0, uint32_t b1) {
    asm("mma.sync.aligned.m16n8k16.row.col.f32.f16.f16.f32 "
        "{%0,%1,%2,%3},{%4,%5,%6,%7},{%8,%9},{%0,%1,%2,%3};"
        : "+f"(c[0]), "+f"(c[1]), "+f"(c[2]), "+f"(c[3])
        : "r"(a[0]), "r"(a[1]), "r"(a[2]), "r"(a[3]), "r"(b0), "r"(b1));
}

static __device__ __forceinline__ float4 pix_math(float rr, float gg, float bb) {
    float r  = fminf(fmaxf(fmaf(rr, 0.5f, 0.5f), 0.f), 1.f);
    float g  = fminf(fmaxf(fmaf(gg, 0.5f, 0.5f), 0.f), 1.f);
    float bl = fminf(fmaxf(fmaf(bb, 0.5f, 0.5f), 0.f), 1.f);
    float iy = sqrtf(fmaf(r, r, fmaf(g, g, fmaf(bl, bl, EPSV))));
    float lr = __logf(r + EPSV), lg = __logf(g + EPSV), lb = __logf(bl + EPSV);
    return make_float4(lr - lg, lr - lb, lg - lb, sqrtf(iy));   // w = sqrt(Iy)
}

__global__ void __launch_bounds__(256, 2)
hist_kernel(const float* __restrict__ rgbd) {
    extern __shared__ char dsm[];                     // 2 operand stages
    __shared__ __align__(16) float    sd[2][3][64];   // d01/d02/d12, x2 buf
    __shared__ __align__(16) uint32_t sw2[2][32];     // half2-packed w pairs

    const uint32_t smb = s2u(dsm);
    const int tid  = threadIdx.x;
    const int lane = tid & 31;
    const int w    = tid >> 5;
    const int b    = blockIdx.x / PARTS;
    const int part = blockIdx.x % PARTS;
    const int start = (int)((long long)part       * NPIX / PARTS);
    const int end   = (int)((long long)(part + 1) * NPIX / PARTS);
    const float* R  = rgbd + (size_t)b * 4 * NPIX;

    // ---- producer mapping: vec = tid>>6 in 0..2 -> panel; 3 = prep warps ----
    const int   vec  = tid >> 6;
    const int   bin  = tid & 63;
    const float negd = 150.0f - (float)bin * QSTEP;
    const ull NEGD2 = pk2(negd);
    const ull C50   = pk2(50.0f);
    const ull ONE2  = pk2(1.0f);
    const int swp   = bin & 7;
    const uint32_t dst = (uint32_t)((vec < 3 ? vec : 0) * 8192 + bin * 128);

    // ---- consumer mapping: warp (rg,cg): 3 rowtiles x 4 coltiles ----
    const int rg = w >> 1;            // 0..3  (rowtiles 3rg..3rg+2 of 12)
    const int cg = w & 1;             // 0..1  (cols 32cg..32cg+31)
    uint32_t byteA[3];
#pragma unroll
    for (int i = 0; i < 3; ++i) {
        const int rt  = 3 * rg + i;
        const int mtx = (rt < 4) ? 0 : ((rt < 8) ? 1 : 2);
        const uint32_t apan = (mtx == 2) ? P1_OFF : P0_OFF;
        const int rowp = 16 * rt - 64 * mtx + (lane & 7) + 8 * ((lane >> 3) & 1);
        byteA[i] = apan + (uint32_t)rowp * 128;
    }
    const int swA   = lane & 7;            // rowtile bases are multiples of 16
    const int koffA = lane >> 4;
    const int colB  = 32 * cg + (lane & 7) + ((lane >> 1) & 8);
    const int koffB = (lane >> 3) & 1;
    const uint32_t bB2 = P1_OFF + (uint32_t)colB * 128;   // q2 frags
    const uint32_t bB3 = P2_OFF + (uint32_t)colB * 128;   // q3 frags
    const bool useQ2 = (rg <= 1);
    const bool useQ3 = (rg >= 1);

    float acc[3][4][4];
#pragma unroll
    for (int i = 0; i < 3; ++i)
#pragma unroll
        for (int t = 0; t < 4; ++t)
#pragma unroll
            for (int k = 0; k < 4; ++k) acc[i][t][k] = 0.f;

    const int nch = (end - start + KC - 1) / KC;

    // pixel prep for chunk 0 (warps 6,7)
    if (tid >= 192) {
        const int q = tid - 192;
        const int px = start + q;
        float4 P = make_float4(0.f, 0.f, 0.f, 0.f);
        if (px < end) P = pix_math(R[px], R[NPIX + px], R[2 * NPIX + px]);
        sd[0][0][q] = P.x; sd[0][1][q] = P.y; sd[0][2][q] = P.z;
        const float wo = __shfl_xor_sync(0xffffffffu, P.w, 1);
        if (!(q & 1)) sw2[0][q >> 1] = packh2(P.w, wo);
    }
    __syncthreads();

    for (int c = 0; c < nch; ++c) {
        const int buf = c & 1;
        const uint32_t stg = smb + buf * STAGEB;

        // early LDG for next chunk's pixels (prep warps)
        float rr = 0.f, gg = 0.f, bb = 0.f;
        int pvalid = 0;
        if (tid >= 192 && c + 1 < nch) {
            const int px = start + (c + 1) * KC + (tid - 192);
            if (px < end) {
                pvalid = 1;
                rr = R[px]; gg = R[NPIX + px]; bb = R[2 * NPIX + px];
            }
        }

        // ---- produce: 8 blocks of 8 pixels (4 pairs), one STS.128 each ----
        if (vec < 3) {
#pragma unroll
            for (int j = 0; j < 8; ++j) {
                const ulonglong2 dP01 = *(const ulonglong2*)&sd[buf][vec][8 * j];
                const ulonglong2 dP23 = *(const ulonglong2*)&sd[buf][vec][8 * j + 4];
                const uint4 wq = *(const uint4*)&sw2[buf][4 * j];

                ull q2, e2;
                uint32_t o0, o1, o2, o3;
                q2 = fma2(dP01.x, C50, NEGD2); e2 = fma2(q2, q2, ONE2);
                o0 = hmul2(packh2(rcpa(lo32(e2)), rcpa(hi32(e2))), wq.x);
                q2 = fma2(dP01.y, C50, NEGD2); e2 = fma2(q2, q2, ONE2);
                o1 = hmul2(packh2(rcpa(lo32(e2)), rcpa(hi32(e2))), wq.y);
                q2 = fma2(dP23.x, C50, NEGD2); e2 = fma2(q2, q2, ONE2);
                o2 = hmul2(packh2(rcpa(lo32(e2)), rcpa(hi32(e2))), wq.z);
                q2 = fma2(dP23.y, C50, NEGD2); e2 = fma2(q2, q2, ONE2);
                o3 = hmul2(packh2(rcpa(lo32(e2)), rcpa(hi32(e2))), wq.w);

                const uint32_t off = (uint32_t)(((j ^ swp) << 4));
                sts128(stg + dst + off, o0, o1, o2, o3);
            }
        }

        // finish pixel prep for next chunk into the other buffers
        if (tid >= 192 && c + 1 < nch) {
            float4 P = make_float4(0.f, 0.f, 0.f, 0.f);
            if (pvalid) P = pix_math(rr, gg, bb);
            const int q = tid - 192;
            sd[buf ^ 1][0][q] = P.x; sd[buf ^ 1][1][q] = P.y;
            sd[buf ^ 1][2][q] = P.z;
            const float wo = __shfl_xor_sync(0xffffffffu, P.w, 1);
            if (!(q & 1)) sw2[buf ^ 1][q >> 1] = packh2(P.w, wo);
        }
        __syncthreads();

        // ---- MMA: 4 k16 steps; per-warp B panel dedup ----
#pragma unroll
        for (int ks = 0; ks < 4; ++ks) {
            uint32_t a[3][4], b2[8], b3[8];
            const uint32_t kxA = (uint32_t)(((2 * ks + koffA) ^ swA) << 4);
            const uint32_t kxB = (uint32_t)(((2 * ks + koffB) ^ swA) << 4);
#pragma unroll
            for (int i = 0; i < 3; ++i)
                ldmx4(a[i][0], a[i][1], a[i][2], a[i][3], stg + byteA[i] + kxA);
            if (useQ2) {
                ldmx4(b2[0], b2[1], b2[2], b2[3], stg + bB2 + kxB);
                ldmx4(b2[4], b2[5], b2[6], b2[7], stg + bB2 + 16 * 128 + kxB);
            }
            if (useQ3) {
                ldmx4(b3[0], b3[1], b3[2], b3[3], stg + bB3 + kxB);
                ldmx4(b3[4], b3[5], b3[6], b3[7], stg + bB3 + 16 * 128 + kxB);
            }
#pragma unroll
            for (int i = 0; i < 3; ++i) {
                if (3 * rg + i < 4) {
#pragma unroll
                    for (int t = 0; t < 4; ++t)
                        mma16(acc[i][t], a[i], b2[2 * t], b2[2 * t + 1]);
                } else {
#pragma unroll
                    for (int t = 0; t < 4; ++t)
                        mma16(acc[i][t], a[i], b3[2 * t], b3[2 * t + 1]);
                }
            }
        }
    }

    // ---- per-batch mass for normalization ----
    float lsum = 0.f;
#pragma unroll
    for (int i = 0; i < 3; ++i)
#pragma unroll
        for (int t = 0; t < 4; ++t)
#pragma unroll
            for (int k = 0; k < 4; ++k) lsum += acc[i][t][k];
#pragma unroll
    for (int o = 16; o > 0; o >>= 1) lsum += __shfl_xor_sync(~0u, lsum, o);
    if (lane == 0) atomicAdd(&g_sum[b], lsum);

    // ---- flush partial G with flips applied (pre-flipped storage) ----
    float* Gb = g_G + (size_t)b * 3 * 4096;
#pragma unroll
    for (int i = 0; i < 3; ++i) {
        const int rt  = 3 * rg + i;
        const int mtx = (rt < 4) ? 0 : ((rt < 8) ? 1 : 2);
        const int urow = 16 * rt - 64 * mtx + (lane >> 2);
        float* Gm = Gb + mtx * 4096;
#pragma unroll
        for (int t = 0; t < 4; ++t) {
            const int c0 = 32 * cg + 8 * t + 2 * (lane & 3);
            if (mtx == 0) {
                float* p0 = Gm + urow * 64 + c0;
                atomicAdd(p0,       acc[i][t][0]);
                atomicAdd(p0 + 1,   acc[i][t][1]);
                atomicAdd(p0 + 512, acc[i][t][2]);
                atomicAdd(p0 + 513, acc[i][t][3]);
            } else if (mtx == 1) {        // row flip
                float* p0 = Gm + (63 - urow) * 64 + c0;
                atomicAdd(p0,       acc[i][t][0]);
                atomicAdd(p0 + 1,   acc[i][t][1]);
                atomicAdd(p0 - 512, acc[i][t][2]);
                atomicAdd(p0 - 511, acc[i][t][3]);
            } else {                      // row + col flip
                float* p0 = Gm + (63 - urow) * 64 + (63 - c0);
                atomicAdd(p0,       acc[i][t][0]);
                atomicAdd(p0 - 1,   acc[i][t][1]);
                atomicAdd(p0 - 512, acc[i][t][2]);
                atomicAdd(p0 - 513, acc[i][t][3]);
            }
        }
    }
}

// ---- Hellinger: 96 CTAs, linear float4; re-zeroes g_G; last CTA finalizes ----
__global__ void hell_kernel(const float* __restrict__ th,
                            float* __restrict__ out, int B) {
    __shared__ float sh[8];
    const int bc  = blockIdx.x >> 2;      // batch*3 + matrix
    const int sub = blockIdx.x & 3;       // quarter
    const int b   = bc / 3, c = bc % 3;
    const float inv = 1.0f / (g_sum[b] + EPSV);
    const int off = c * 4096 + (sub * 256 + threadIdx.x) * 4;
    float* Gp = g_G + (size_t)b * 3 * 4096 + off;

    const float4 h4 = *(const float4*)Gp;
    const float4 t4 = *(const float4*)(th + off);
    *(float4*)Gp = make_float4(0.f, 0.f, 0.f, 0.f);   // reset for replay

    float d0 = sqrtf(t4.x) - sqrtf(h4.x * inv);
    float d1 = sqrtf(t4.y) - sqrtf(h4.y * inv);
    float d2 = sqrtf(t4.z) - sqrtf(h4.z * inv);
    float d3 = sqrtf(t4.w) - sqrtf(h4.w * inv);
    float a = fmaf(d0, d0, fmaf(d1, d1, fmaf(d2, d2, d3 * d3)));

#pragma unroll
    for (int o = 16; o > 0; o >>= 1) a += __shfl_xor_sync(~0u, a, o);
    if ((threadIdx.x & 31) == 0) sh[threadIdx.x >> 5] = a;
    __syncthreads();
    if (threadIdx.x == 0) {
        float s = 0.f;
#pragma unroll
        for (int i = 0; i < 8; ++i) s += sh[i];
        atomicAdd(&g_acc, s);
        __threadfence();
        const unsigned rank = atomicAdd(&g_done, 1u);
        if (rank == (unsigned)(12 * B - 1)) {      // last CTA finalizes
            __threadfence();
            out[0] = sqrtf(g_acc) * (0.70710678118654752f / (float)B);
            g_acc = 0.f;
            g_done = 0u;
#pragma unroll
            for (int i = 0; i < 8; ++i) g_sum[i] = 0.f;
        }
    }
}

extern "C" void kernel_launch(void* const* d_in, const int* in_sizes, int n_in,
                              void* d_out, int out_size) {
    const float* rgbd = (const float*)d_in[0];
    const float* th   = (const float*)d_in[1];
    float* out        = (float*)d_out;

    const int B = in_sizes[0] / (4 * NPIX);   // 8

    cudaFuncSetAttribute(hist_kernel,
                         cudaFuncAttributeMaxDynamicSharedMemorySize, DSMEMB);
    hist_kernel<<<B * PARTS, 256, DSMEMB>>>(rgbd);
    hell_kernel<<<B * 12, 256>>>(th, out, B);
}

// round 12
// speedup vs baseline: 1.3083x; 1.3083x over previous
#include <cuda_runtime.h>
#include <cuda_fp16.h>
#include <cstdint>

// HistoGAN histogram loss via mma.sync f16 + ldmatrix, K-contiguous swizzled
// operands, KC=128 (two 64-px sub-panels per stage), double-buffered stages,
// one sync per chunk. Producer uses packed fma.rn.f32x2 + f16x2 w-fold.
//
// Symmetric intensity fold: w = sqrt(Iy); panels q1=w*k01, q2=w*k02, q3=w*k12.
//   G_AB = q1 x q2^T, G_AC = q1 x q3^T, G_BC = q2 x q3^T   (w^2 = Iy)
// Flips applied AT THE EPILOGUE (pre-flipped storage):
//   hist0[u,v]=G_AB[u,v]; hist1[u,v]=G_AC[63-u,v]; hist2[u,v]=G_BC[63-u,63-v]
//
// Stage layout: [q1a q2a q3a | q1b q2b q3b], each sub-panel 8KB with 128B rows
// and 16B-block swizzle blk' = blk ^ (row & 7) (identical to proven KC=64).

#define EPSV  (6.4f / 255.0f)
#define NPIX  65536
#define PARTS 37
#define QSTEP 4.761904761904762f   /* 300/63 */
#define KC    128

#define P0_OFF  0
#define P1_OFF  8192
#define P2_OFF  16384
#define SUBB    24576               /* second 64-px sub-panel group */
#define STAGEB  49152
#define DSMEMB  (2 * STAGEB)

typedef unsigned long long ull;

__device__ float g_G[8 * 3 * 4096];   // [B][3][64][64] pre-flipped hist
__device__ float g_sum[8];            // per-batch total mass
__device__ float g_acc;               // Hellinger sum accumulator
__device__ unsigned g_done;           // hell CTA completion counter

static __device__ __forceinline__ float rcpa(float x) {
    float r; asm("rcp.approx.f32 %0, %1;" : "=f"(r) : "f"(x)); return r;
}
static __device__ __forceinline__ uint32_t s2u(const void* p) {
    uint32_t a;
    asm("{ .reg .u64 t; cvta.to.shared.u64 t, %1; cvt.u32.u64 %0, t; }"
        : "=r"(a) : "l"(p));
    return a;
}
static __device__ __forceinline__ uint32_t packh2(float lo, float hi) {
    __half2 h = __floats2half2_rn(lo, hi);
    return *(uint32_t*)&h;
}
static __device__ __forceinline__ ull pk2(float v) {
    ull r; asm("mov.b64 %0, {%1, %1};" : "=l"(r) : "f"(v)); return r;
}
static __device__ __forceinline__ ull fma2(ull a, ull b, ull c) {
    ull d; asm("fma.rn.f32x2 %0, %1, %2, %3;" : "=l"(d)
               : "l"(a), "l"(b), "l"(c));
    return d;
}
static __device__ __forceinline__ float lo32(ull a) {
    return __uint_as_float((uint32_t)a);
}
static __device__ __forceinline__ float hi32(ull a) {
    return __uint_as_float((uint32_t)(a >> 32));
}
static __device__ __forceinline__ uint32_t hmul2(uint32_t a, uint32_t b) {
    uint32_t d; asm("mul.rn.f16x2 %0, %1, %2;" : "=r"(d) : "r"(a), "r"(b));
    return d;
}
static __device__ __forceinline__ void sts128(uint32_t addr, uint32_t w0,
        uint32_t w1, uint32_t w2, uint32_t w3) {
    asm volatile("st.shared.v4.b32 [%0], {%1,%2,%3,%4};"
        :: "r"(addr), "r"(w0), "r"(w1), "r"(w2), "r"(w3));
}
static __device__ __forceinline__ void ldmx4(uint32_t& r0, uint32_t& r1,
        uint32_t& r2, uint32_t& r3, uint32_t addr) {
    asm volatile("ldmatrix.sync.aligned.m8n8.x4.shared.b16 {%0,%1,%2,%3}, [%4];"
        : "=r"(r0), "=r"(r1), "=r"(r2), "=r"(r3) : "r"(addr));
}
static __device__ __forceinline__ void mma16(float* c,
        uint32_t a0, uint32_t a1, uint32_t a2, uint32_t a3,
        uint32_t b0, uint32_t b1) {
    asm("mma.sync.aligned.m16n8k16.row.col.f32.f16.f16.f32 "
        "{%0,%1,%2,%3},{%4,%5,%6,%7},{%8,%9},{%0,%1,%2,%3};"
        : "+f"(c[0]), "+f"(c[1]), "+f"(c[2]), "+f"(c[3])
        : "r"(a0), "r"(a1), "r"(a2), "r"(a3), "r"(b0), "r"(b1));
}

static __device__ __forceinline__ float4 pix_math(float rr, float gg, float bb) {
    float r  = fminf(fmaxf(fmaf(rr, 0.5f, 0.5f), 0.f), 1.f);
    float g  = fminf(fmaxf(fmaf(gg, 0.5f, 0.5f), 0.f), 1.f);
    float bl = fminf(fmaxf(fmaf(bb, 0.5f, 0.5f), 0.f), 1.f);
    float iy = sqrtf(fmaf(r, r, fmaf(g, g, fmaf(bl, bl, EPSV))));
    float lr = __logf(r + EPSV), lg = __logf(g + EPSV), lb = __logf(bl + EPSV);
    return make_float4(lr - lg, lr - lb, lg - lb, sqrtf(iy));   // w = sqrt(Iy)
}

__global__ void __launch_bounds__(192, 2)
hist_kernel(const float* __restrict__ rgbd) {
    extern __shared__ char dsm[];                     // 2 operand stages
    __shared__ __align__(16) float    sd[2][3][KC];   // d01/d02/d12, x2 buf
    __shared__ __align__(16) uint32_t sw2[2][KC / 2]; // half2-packed w pairs

    const uint32_t smb = s2u(dsm);
    const int tid  = threadIdx.x;
    const int lane = tid & 31;
    const int w    = tid >> 5;
    const int b    = blockIdx.x / PARTS;
    const int part = blockIdx.x % PARTS;
    const int start = (int)((long long)part       * NPIX / PARTS);
    const int end   = (int)((long long)(part + 1) * NPIX / PARTS);
    const float* R  = rgbd + (size_t)b * 4 * NPIX;

    // ---- producer mapping: vec = tid>>6 -> panel q(vec+1) ----
    const int   vec  = tid >> 6;
    const int   bin  = tid & 63;
    const float negd = 150.0f - (float)bin * QSTEP;
    const ull NEGD2 = pk2(negd);
    const ull C50   = pk2(50.0f);
    const ull ONE2  = pk2(1.0f);
    const int swp   = bin & 7;
    const uint32_t dst = (uint32_t)(vec * 8192 + bin * 128);

    // ---- consumer mapping: warp -> matrix m, row-half rh ----
    const int m  = w >> 1;                 // 0=AB(q1xq2), 1=AC(q1xq3), 2=BC(q2xq3)
    const int rh = w & 1;
    const uint32_t Apanel = (m == 2) ? P1_OFF : P0_OFF;
    const uint32_t Boff   = (m == 0) ? P1_OFF : P2_OFF;
    const int rip   = 32 * rh + (lane & 7) + 8 * ((lane >> 3) & 1);
    const int swA   = rip & 7;
    const int koffA = lane >> 4;
    const uint32_t byteA0 = Apanel + (uint32_t)rip * 128;
    const uint32_t byteA1 = byteA0 + 16 * 128;
    const int colB  = (lane & 7) + ((lane >> 1) & 8);
    const int swB   = lane & 7;
    const int koffB = (lane >> 3) & 1;
    const uint32_t byteBbase = Boff + (uint32_t)colB * 128;

    float acc[2][8][4];
#pragma unroll
    for (int s = 0; s < 2; ++s)
#pragma unroll
        for (int t = 0; t < 8; ++t)
#pragma unroll
            for (int i = 0; i < 4; ++i) acc[s][t][i] = 0.f;

    const int nch = (end - start + KC - 1) / KC;

    // pixel prep for chunk 0 (warps 4,5; 2 pixels per thread: q and q+64)
    if (tid >= 128) {
        const int q = tid - 128;
#pragma unroll
        for (int h = 0; h < 2; ++h) {
            const int qq = q + 64 * h;
            const int px = start + qq;
            float4 P = make_float4(0.f, 0.f, 0.f, 0.f);
            if (px < end) P = pix_math(R[px], R[NPIX + px], R[2 * NPIX + px]);
            sd[0][0][qq] = P.x; sd[0][1][qq] = P.y; sd[0][2][qq] = P.z;
            const float wo = __shfl_xor_sync(0xffffffffu, P.w, 1);
            if (!(q & 1)) sw2[0][qq >> 1] = packh2(P.w, wo);
        }
    }
    __syncthreads();

    for (int c = 0; c < nch; ++c) {
        const int buf = c & 1;
        const uint32_t stg = smb + buf * STAGEB;

        // early LDG for next chunk's pixels (2 per prep thread)
        float rr[2], gg[2], bb[2];
        int pvalid[2] = {0, 0};
        if (tid >= 128 && c + 1 < nch) {
            const int q = tid - 128;
#pragma unroll
            for (int h = 0; h < 2; ++h) {
                const int px = start + (c + 1) * KC + q + 64 * h;
                if (px < end) {
                    pvalid[h] = 1;
                    rr[h] = R[px]; gg[h] = R[NPIX + px]; bb[h] = R[2 * NPIX + px];
                }
            }
        }

        // ---- produce: 16 blocks of 8 pixels (4 pairs), one STS.128 each ----
#pragma unroll
        for (int j = 0; j < 16; ++j) {
            const ulonglong2 dP01 = *(const ulonglong2*)&sd[buf][vec][8 * j];
            const ulonglong2 dP23 = *(const ulonglong2*)&sd[buf][vec][8 * j + 4];
            const uint4 wq = *(const uint4*)&sw2[buf][4 * j];

            ull q2, e2;
            uint32_t o0, o1, o2, o3;
            q2 = fma2(dP01.x, C50, NEGD2); e2 = fma2(q2, q2, ONE2);
            o0 = hmul2(packh2(rcpa(lo32(e2)), rcpa(hi32(e2))), wq.x);
            q2 = fma2(dP01.y, C50, NEGD2); e2 = fma2(q2, q2, ONE2);
            o1 = hmul2(packh2(rcpa(lo32(e2)), rcpa(hi32(e2))), wq.y);
            q2 = fma2(dP23.x, C50, NEGD2); e2 = fma2(q2, q2, ONE2);
            o2 = hmul2(packh2(rcpa(lo32(e2)), rcpa(hi32(e2))), wq.z);
            q2 = fma2(dP23.y, C50, NEGD2); e2 = fma2(q2, q2, ONE2);
            o3 = hmul2(packh2(rcpa(lo32(e2)), rcpa(hi32(e2))), wq.w);

            const uint32_t off = (uint32_t)((j & 8) ? SUBB : 0) +
                                 (uint32_t)((((j & 7) ^ swp) << 4));
            sts128(stg + dst + off, o0, o1, o2, o3);
        }

        // finish pixel prep for next chunk into the other buffers
        if (tid >= 128 && c + 1 < nch) {
            const int q = tid - 128;
#pragma unroll
            for (int h = 0; h < 2; ++h) {
                float4 P = make_float4(0.f, 0.f, 0.f, 0.f);
                if (pvalid[h]) P = pix_math(rr[h], gg[h], bb[h]);
                const int qq = q + 64 * h;
                sd[buf ^ 1][0][qq] = P.x; sd[buf ^ 1][1][qq] = P.y;
                sd[buf ^ 1][2][qq] = P.z;
                const float wo = __shfl_xor_sync(0xffffffffu, P.w, 1);
                if (!(q & 1)) sw2[buf ^ 1][qq >> 1] = packh2(P.w, wo);
            }
        }
        __syncthreads();

        // ---- MMA: 8 k16 steps via ldmatrix.x4 (two sub-panel groups) ----
#pragma unroll
        for (int ks = 0; ks < 8; ++ks) {
            const uint32_t stgk = stg + ((ks & 4) ? SUBB : 0);
            const int kk = ks & 3;
            uint32_t a0[4], a1[4], bm[4][4];
            const uint32_t kxA = (uint32_t)(((2 * kk + koffA) ^ swA) << 4);
            const uint32_t kxB = (uint32_t)(((2 * kk + koffB) ^ swB) << 4);
            ldmx4(a0[0], a0[1], a0[2], a0[3], stgk + byteA0 + kxA);
            ldmx4(a1[0], a1[1], a1[2], a1[3], stgk + byteA1 + kxA);
#pragma unroll
            for (int j = 0; j < 4; ++j)
                ldmx4(bm[j][0], bm[j][1], bm[j][2], bm[j][3],
                      stgk + byteBbase + (uint32_t)(16 * j * 128) + kxB);
#pragma unroll
            for (int j = 0; j < 4; ++j) {
                mma16(acc[0][2 * j],     a0[0], a0[1], a0[2], a0[3], bm[j][0], bm[j][1]);
                mma16(acc[0][2 * j + 1], a0[0], a0[1], a0[2], a0[3], bm[j][2], bm[j][3]);
                mma16(acc[1][2 * j],     a1[0], a1[1], a1[2], a1[3], bm[j][0], bm[j][1]);
                mma16(acc[1][2 * j + 1], a1[0], a1[1], a1[2], a1[3], bm[j][2], bm[j][3]);
            }
        }
    }

    // ---- per-batch mass for normalization ----
    float lsum = 0.f;
#pragma unroll
    for (int s = 0; s < 2; ++s)
#pragma unroll
        for (int t = 0; t < 8; ++t)
#pragma unroll
            for (int i = 0; i < 4; ++i) lsum += acc[s][t][i];
#pragma unroll
    for (int o = 16; o > 0; o >>= 1) lsum += __shfl_xor_sync(~0u, lsum, o);
    if (lane == 0) atomicAdd(&g_sum[b], lsum);

    // ---- flush partial G with flips applied (pre-flipped storage) ----
    float* Gm = g_G + (size_t)b * 3 * 4096 + m * 4096;
    const int urow = 32 * rh + (lane >> 2);
    const int col  = 2 * (lane & 3);
#pragma unroll
    for (int s = 0; s < 2; ++s) {
#pragma unroll
        for (int t = 0; t < 8; ++t) {
            const int r0 = urow + 16 * s;
            const int c0 = 8 * t + col;
            if (m == 0) {
                float* p0 = Gm + r0 * 64 + c0;
                atomicAdd(p0,           acc[s][t][0]);
                atomicAdd(p0 + 1,       acc[s][t][1]);
                atomicAdd(p0 + 512,     acc[s][t][2]);
                atomicAdd(p0 + 513,     acc[s][t][3]);
            } else if (m == 1) {        // row flip
                float* p0 = Gm + (63 - r0) * 64 + c0;
                atomicAdd(p0,           acc[s][t][0]);
                atomicAdd(p0 + 1,       acc[s][t][1]);
                atomicAdd(p0 - 512,     acc[s][t][2]);
                atomicAdd(p0 - 511,     acc[s][t][3]);
            } else {                    // row + col flip
                float* p0 = Gm + (63 - r0) * 64 + (63 - c0);
                atomicAdd(p0,           acc[s][t][0]);
                atomicAdd(p0 - 1,       acc[s][t][1]);
                atomicAdd(p0 - 512,     acc[s][t][2]);
                atomicAdd(p0 - 513,     acc[s][t][3]);
            }
        }
    }
}

// ---- Hellinger: 96 CTAs, linear float4; re-zeroes g_G; last CTA finalizes ----
__global__ void hell_kernel(const float* __restrict__ th,
                            float* __restrict__ out, int B) {
    __shared__ float sh[8];
    const int bc  = blockIdx.x >> 2;      // batch*3 + matrix
    const int sub = blockIdx.x & 3;       // quarter
    const int b   = bc / 3, c = bc % 3;
    const float inv = 1.0f / (g_sum[b] + EPSV);
    const int off = c * 4096 + (sub * 256 + threadIdx.x) * 4;
    float* Gp = g_G + (size_t)b * 3 * 4096 + off;

    const float4 h4 = *(const float4*)Gp;
    const float4 t4 = *(const float4*)(th + off);
    *(float4*)Gp = make_float4(0.f, 0.f, 0.f, 0.f);   // reset for replay

    float d0 = sqrtf(t4.x) - sqrtf(h4.x * inv);
    float d1 = sqrtf(t4.y) - sqrtf(h4.y * inv);
    float d2 = sqrtf(t4.z) - sqrtf(h4.z * inv);
    float d3 = sqrtf(t4.w) - sqrtf(h4.w * inv);
    float a = fmaf(d0, d0, fmaf(d1, d1, fmaf(d2, d2, d3 * d3)));

#pragma unroll
    for (int o = 16; o > 0; o >>= 1) a += __shfl_xor_sync(~0u, a, o);
    if ((threadIdx.x & 31) == 0) sh[threadIdx.x >> 5] = a;
    __syncthreads();
    if (threadIdx.x == 0) {
        float s = 0.f;
#pragma unroll
        for (int i = 0; i < 8; ++i) s += sh[i];
        atomicAdd(&g_acc, s);
        __threadfence();
        const unsigned rank = atomicAdd(&g_done, 1u);
        if (rank == (unsigned)(12 * B - 1)) {      // last CTA finalizes
            __threadfence();
            out[0] = sqrtf(g_acc) * (0.70710678118654752f / (float)B);
            g_acc = 0.f;
            g_done = 0u;
#pragma unroll
            for (int i = 0; i < 8; ++i) g_sum[i] = 0.f;
        }
    }
}

extern "C" void kernel_launch(void* const* d_in, const int* in_sizes, int n_in,
                              void* d_out, int out_size) {
    const float* rgbd = (const float*)d_in[0];
    const float* th   = (const float*)d_in[1];
    float* out        = (float*)d_out;

    const int B = in_sizes[0] / (4 * NPIX);   // 8

    cudaFuncSetAttribute(hist_kernel,
                         cudaFuncAttributeMaxDynamicSharedMemorySize, DSMEMB);
    hist_kernel<<<B * PARTS, 192, DSMEMB>>>(rgbd);
    hell_kernel<<<B * 12, 256>>>(th, out, B);
}